// round 3
// baseline (speedup 1.0000x reference)
#include <cuda_runtime.h>
#include <cstdint>

// ---------------------------------------------------------------------------
// GCL layer:  edge MLP (gather, concat, Lin 256->128, SiLU, Lin 128->128, SiLU)
//             -> scatter-sum / 100 -> node MLP (concat, Lin 256->128, SiLU,
//             Lin 128->128) + residual.
// Outputs (in d_out): h_out [N,128] followed by mij [E,128], fp32.
// ---------------------------------------------------------------------------

#define DD 128
#define TILE 128
#define NTHREADS 256
#define MAXN 50000
#define NORM_INV 0.01f

// smem layout (floats): Xs[128][33] | Ws[32][128] | Hs[128][130] | Ri[128] Ci[128] (ints)
#define XS_STRIDE 33
#define HS_STRIDE 130
#define SMEM_FLOATS (TILE * XS_STRIDE + 32 * DD + TILE * HS_STRIDE)
#define SMEM_BYTES (SMEM_FLOATS * 4 + 2 * TILE * 4)

__device__ float g_agg[(size_t)MAXN * DD];   // scatter-sum scratch
__device__ int g_is64;                       // edge_index dtype flag

// ---- packed fp32x2 helpers (sm_100+ FFMA2 — full-rate fp32) ----
__device__ __forceinline__ void fma2(unsigned long long& d,
                                     unsigned long long a,
                                     unsigned long long b) {
    asm("fma.rn.f32x2 %0, %1, %2, %0;" : "+l"(d) : "l"(a), "l"(b));
}
__device__ __forceinline__ unsigned long long bcast2(unsigned int a) {
    unsigned long long r;
    asm("mov.b64 %0, {%1, %2};" : "=l"(r) : "r"(a), "r"(a));
    return r;
}
__device__ __forceinline__ void unpack2(unsigned long long v, float& lo, float& hi) {
    unsigned int a, b;
    asm("mov.b64 {%0, %1}, %2;" : "=r"(a), "=r"(b) : "l"(v));
    lo = __uint_as_float(a);
    hi = __uint_as_float(b);
}
__device__ __forceinline__ float silu_f(float x) {
    return x / (1.0f + __expf(-x));
}

// 32-deep K-chunk of a 128x128 tile GEMM. Each thread owns 8 rows x 8 cols,
// accumulators packed as 4 f32x2 per row (pairs along N).
__device__ __forceinline__ void mma_chunk(unsigned long long acc[8][4],
                                          const float* __restrict__ A, int astride,
                                          const float* __restrict__ Ws,
                                          int te, int tn) {
#pragma unroll 4
    for (int kk = 0; kk < 32; kk++) {
        const float* wrow = Ws + kk * DD + tn * 8;
        ulonglong2 q0 = *(const ulonglong2*)(wrow);       // 4 floats = 2 packed
        ulonglong2 q1 = *(const ulonglong2*)(wrow + 4);
#pragma unroll
        for (int i = 0; i < 8; i++) {
            unsigned int au = __float_as_uint(A[(te * 8 + i) * astride + kk]);
            unsigned long long ap = bcast2(au);
            fma2(acc[i][0], ap, q0.x);
            fma2(acc[i][1], ap, q0.y);
            fma2(acc[i][2], ap, q1.x);
            fma2(acc[i][3], ap, q1.y);
        }
    }
}

// ---------------------------------------------------------------------------
__global__ void detect_dtype_kernel(const int* __restrict__ ei, int force64) {
    if (threadIdx.x == 0 && blockIdx.x == 0) {
        if (force64) { g_is64 = 1; return; }
        // int64 indices < 2^31 and nonnegative => every odd 32-bit word is 0.
        int is64 = 1;
        for (int i = 0; i < 64; i++) {
            if (ei[2 * i + 1] != 0) { is64 = 0; break; }
        }
        g_is64 = is64;
    }
}

__global__ void zero_agg_kernel(int n4) {
    int i = blockIdx.x * blockDim.x + threadIdx.x;
    if (i < n4) ((float4*)g_agg)[i] = make_float4(0.f, 0.f, 0.f, 0.f);
}

// ---------------------------------------------------------------------------
__global__ void __launch_bounds__(NTHREADS, 2)
edge_kernel(const float* __restrict__ h, const void* __restrict__ ei,
            const float* __restrict__ We1, const float* __restrict__ be1,
            const float* __restrict__ We2, const float* __restrict__ be2,
            float* __restrict__ out_m, int N, int E) {
    extern __shared__ float sm[];
    float* Xs = sm;                           // [128][33]
    float* Ws = Xs + TILE * XS_STRIDE;        // [32][128]
    float* Hs = Ws + 32 * DD;                 // [128][130]
    int* Ri = (int*)(Hs + TILE * HS_STRIDE);
    int* Ci = Ri + TILE;

    const int tid = threadIdx.x;
    const int tn = tid & 15;    // 16 col-groups of 8
    const int te = tid >> 4;    // 16 row-groups of 8
    const long long eb = (long long)blockIdx.x * TILE;

    // --- load + clamp edge indices for this tile ---
    if (tid < TILE) {
        long long e = eb + tid;
        if (e >= E) e = E - 1;
        int r, c;
        if (g_is64) {
            const long long* p = (const long long*)ei;
            r = (int)p[e];
            c = (int)p[(long long)E + e];
        } else {
            const int* p = (const int*)ei;
            r = p[e];
            c = p[E + e];
        }
        r = min(max(r, 0), N - 1);
        c = min(max(c, 0), N - 1);
        Ri[tid] = r;
        Ci[tid] = c;
    }

    float b1v[8], b2v[8];
    {
        float4 t0 = *(const float4*)(be1 + tn * 8);
        float4 t1 = *(const float4*)(be1 + tn * 8 + 4);
        b1v[0]=t0.x; b1v[1]=t0.y; b1v[2]=t0.z; b1v[3]=t0.w;
        b1v[4]=t1.x; b1v[5]=t1.y; b1v[6]=t1.z; b1v[7]=t1.w;
        float4 u0 = *(const float4*)(be2 + tn * 8);
        float4 u1 = *(const float4*)(be2 + tn * 8 + 4);
        b2v[0]=u0.x; b2v[1]=u0.y; b2v[2]=u0.z; b2v[3]=u0.w;
        b2v[4]=u1.x; b2v[5]=u1.y; b2v[6]=u1.z; b2v[7]=u1.w;
    }

    unsigned long long acc[8][4];
#pragma unroll
    for (int i = 0; i < 8; i++)
#pragma unroll
        for (int j = 0; j < 4; j++) acc[i][j] = 0ULL;

    // --- layer 1: [128 edges, 256] @ We1[256,128], K chunked by 32 ---
#pragma unroll 1
    for (int kc = 0; kc < 8; kc++) {
        __syncthreads();
        const int koff = (kc & 3) * 32;
        const int* idx = (kc < 4) ? Ri : Ci;
        // gather X chunk: 128 edges x 32 floats (1024 float4)
#pragma unroll
        for (int l = 0; l < 4; l++) {
            int lin = tid + l * NTHREADS;
            int e = lin >> 3, seg = lin & 7;
            const float4 v = *(const float4*)(h + (size_t)idx[e] * DD + koff + seg * 4);
            float* dst = Xs + e * XS_STRIDE + seg * 4;
            dst[0] = v.x; dst[1] = v.y; dst[2] = v.z; dst[3] = v.w;
        }
        // stage W1 chunk: 32 x 128
#pragma unroll
        for (int l = 0; l < 4; l++) {
            int lin = tid + l * NTHREADS;
            int kk = lin >> 5, n4 = lin & 31;
            *(float4*)(Ws + kk * DD + n4 * 4) =
                *(const float4*)(We1 + (size_t)(kc * 32 + kk) * DD + n4 * 4);
        }
        __syncthreads();
        mma_chunk(acc, Xs, XS_STRIDE, Ws, te, tn);
    }

    // --- bias + SiLU -> Hs, reset acc ---
#pragma unroll
    for (int i = 0; i < 8; i++) {
        float v[8];
        unpack2(acc[i][0], v[0], v[1]);
        unpack2(acc[i][1], v[2], v[3]);
        unpack2(acc[i][2], v[4], v[5]);
        unpack2(acc[i][3], v[6], v[7]);
#pragma unroll
        for (int j = 0; j < 8; j++)
            Hs[(te * 8 + i) * HS_STRIDE + tn * 8 + j] = silu_f(v[j] + b1v[j]);
#pragma unroll
        for (int j = 0; j < 4; j++) acc[i][j] = 0ULL;
    }

    // --- layer 2: Hs[128,128] @ We2[128,128] ---
#pragma unroll 1
    for (int kc = 0; kc < 4; kc++) {
        __syncthreads();
#pragma unroll
        for (int l = 0; l < 4; l++) {
            int lin = tid + l * NTHREADS;
            int kk = lin >> 5, n4 = lin & 31;
            *(float4*)(Ws + kk * DD + n4 * 4) =
                *(const float4*)(We2 + (size_t)(kc * 32 + kk) * DD + n4 * 4);
        }
        __syncthreads();
        mma_chunk(acc, Hs + kc * 32, HS_STRIDE, Ws, te, tn);
    }

    // --- epilogue: SiLU, write mij, scatter-add into g_agg ---
#pragma unroll
    for (int i = 0; i < 8; i++) {
        long long eg = eb + te * 8 + i;
        if (eg < E) {
            float v[8];
            unpack2(acc[i][0], v[0], v[1]);
            unpack2(acc[i][1], v[2], v[3]);
            unpack2(acc[i][2], v[4], v[5]);
            unpack2(acc[i][3], v[6], v[7]);
#pragma unroll
            for (int j = 0; j < 8; j++) v[j] = silu_f(v[j] + b2v[j]);
            float4* dst = (float4*)(out_m + (size_t)eg * DD + tn * 8);
            dst[0] = make_float4(v[0], v[1], v[2], v[3]);
            dst[1] = make_float4(v[4], v[5], v[6], v[7]);
            float* ap = g_agg + (size_t)Ri[te * 8 + i] * DD + tn * 8;
            asm volatile("red.global.add.v4.f32 [%0], {%1,%2,%3,%4};"
                         :: "l"(ap), "f"(v[0]), "f"(v[1]), "f"(v[2]), "f"(v[3])
                         : "memory");
            asm volatile("red.global.add.v4.f32 [%0], {%1,%2,%3,%4};"
                         :: "l"(ap + 4), "f"(v[4]), "f"(v[5]), "f"(v[6]), "f"(v[7])
                         : "memory");
        }
    }
}

// ---------------------------------------------------------------------------
__global__ void __launch_bounds__(NTHREADS, 2)
node_kernel(const float* __restrict__ h,
            const float* __restrict__ Wn1, const float* __restrict__ bn1,
            const float* __restrict__ Wn2, const float* __restrict__ bn2,
            float* __restrict__ out_h, int N) {
    extern __shared__ float sm[];
    float* Xs = sm;
    float* Ws = Xs + TILE * XS_STRIDE;
    float* Hs = Ws + 32 * DD;

    const int tid = threadIdx.x;
    const int tn = tid & 15;
    const int te = tid >> 4;
    const int nb = blockIdx.x * TILE;

    float b1v[8], b2v[8];
    {
        float4 t0 = *(const float4*)(bn1 + tn * 8);
        float4 t1 = *(const float4*)(bn1 + tn * 8 + 4);
        b1v[0]=t0.x; b1v[1]=t0.y; b1v[2]=t0.z; b1v[3]=t0.w;
        b1v[4]=t1.x; b1v[5]=t1.y; b1v[6]=t1.z; b1v[7]=t1.w;
        float4 u0 = *(const float4*)(bn2 + tn * 8);
        float4 u1 = *(const float4*)(bn2 + tn * 8 + 4);
        b2v[0]=u0.x; b2v[1]=u0.y; b2v[2]=u0.z; b2v[3]=u0.w;
        b2v[4]=u1.x; b2v[5]=u1.y; b2v[6]=u1.z; b2v[7]=u1.w;
    }

    unsigned long long acc[8][4];
#pragma unroll
    for (int i = 0; i < 8; i++)
#pragma unroll
        for (int j = 0; j < 4; j++) acc[i][j] = 0ULL;

    // --- layer 1: [128 nodes, 256] @ Wn1 (first 128 from h, next 128 agg/100)
#pragma unroll 1
    for (int kc = 0; kc < 8; kc++) {
        __syncthreads();
        const int koff = (kc & 3) * 32;
        const bool from_h = (kc < 4);
        const float* src = from_h ? h : (const float*)g_agg;
        const float scale = from_h ? 1.0f : NORM_INV;
#pragma unroll
        for (int l = 0; l < 4; l++) {
            int lin = tid + l * NTHREADS;
            int e = lin >> 3, seg = lin & 7;
            int node = nb + e;
            if (node >= N) node = N - 1;
            float4 v = *(const float4*)(src + (size_t)node * DD + koff + seg * 4);
            float* dst = Xs + e * XS_STRIDE + seg * 4;
            dst[0] = v.x * scale; dst[1] = v.y * scale;
            dst[2] = v.z * scale; dst[3] = v.w * scale;
        }
#pragma unroll
        for (int l = 0; l < 4; l++) {
            int lin = tid + l * NTHREADS;
            int kk = lin >> 5, n4 = lin & 31;
            *(float4*)(Ws + kk * DD + n4 * 4) =
                *(const float4*)(Wn1 + (size_t)(kc * 32 + kk) * DD + n4 * 4);
        }
        __syncthreads();
        mma_chunk(acc, Xs, XS_STRIDE, Ws, te, tn);
    }

#pragma unroll
    for (int i = 0; i < 8; i++) {
        float v[8];
        unpack2(acc[i][0], v[0], v[1]);
        unpack2(acc[i][1], v[2], v[3]);
        unpack2(acc[i][2], v[4], v[5]);
        unpack2(acc[i][3], v[6], v[7]);
#pragma unroll
        for (int j = 0; j < 8; j++)
            Hs[(te * 8 + i) * HS_STRIDE + tn * 8 + j] = silu_f(v[j] + b1v[j]);
#pragma unroll
        for (int j = 0; j < 4; j++) acc[i][j] = 0ULL;
    }

    // --- layer 2 (no activation) ---
#pragma unroll 1
    for (int kc = 0; kc < 4; kc++) {
        __syncthreads();
#pragma unroll
        for (int l = 0; l < 4; l++) {
            int lin = tid + l * NTHREADS;
            int kk = lin >> 5, n4 = lin & 31;
            *(float4*)(Ws + kk * DD + n4 * 4) =
                *(const float4*)(Wn2 + (size_t)(kc * 32 + kk) * DD + n4 * 4);
        }
        __syncthreads();
        mma_chunk(acc, Hs + kc * 32, HS_STRIDE, Ws, te, tn);
    }

    // --- epilogue: + bias + residual h ---
#pragma unroll
    for (int i = 0; i < 8; i++) {
        int node = nb + te * 8 + i;
        if (node < N) {
            float v[8];
            unpack2(acc[i][0], v[0], v[1]);
            unpack2(acc[i][1], v[2], v[3]);
            unpack2(acc[i][2], v[4], v[5]);
            unpack2(acc[i][3], v[6], v[7]);
            const float4 r0 = *(const float4*)(h + (size_t)node * DD + tn * 8);
            const float4 r1 = *(const float4*)(h + (size_t)node * DD + tn * 8 + 4);
            v[0] += b2v[0] + r0.x; v[1] += b2v[1] + r0.y;
            v[2] += b2v[2] + r0.z; v[3] += b2v[3] + r0.w;
            v[4] += b2v[4] + r1.x; v[5] += b2v[5] + r1.y;
            v[6] += b2v[6] + r1.z; v[7] += b2v[7] + r1.w;
            float4* dst = (float4*)(out_h + (size_t)node * DD + tn * 8);
            dst[0] = make_float4(v[0], v[1], v[2], v[3]);
            dst[1] = make_float4(v[4], v[5], v[6], v[7]);
        }
    }
}

// ---------------------------------------------------------------------------
extern "C" void kernel_launch(void* const* d_in, const int* in_sizes, int n_in,
                              void* d_out, int out_size) {
    const float* h   = (const float*)d_in[0];
    const void*  ei  = d_in[1];
    const float* We1 = (const float*)d_in[2];
    const float* be1 = (const float*)d_in[3];
    const float* We2 = (const float*)d_in[4];
    const float* be2 = (const float*)d_in[5];
    const float* Wn1 = (const float*)d_in[6];
    const float* bn1 = (const float*)d_in[7];
    const float* Wn2 = (const float*)d_in[8];
    const float* bn2 = (const float*)d_in[9];

    const int N = in_sizes[0] / DD;
    // E derived from output size: out = h_out[N,128] ++ mij[E,128].
    // This is dtype-independent, unlike in_sizes[1] whose element count
    // depends on whether the harness surfaces int64 as 1 or 2 words.
    const int E = out_size / DD - N;
    // If edge_index element count is 4*E, the int64 array is being counted
    // in 32-bit words -> force 64-bit index reads.
    const int force64 = (in_sizes[1] == 4 * E) ? 1 : 0;

    float* out_h = (float*)d_out;
    float* out_m = out_h + (size_t)N * DD;

    cudaFuncSetAttribute(edge_kernel,
                         cudaFuncAttributeMaxDynamicSharedMemorySize, SMEM_BYTES);
    cudaFuncSetAttribute(node_kernel,
                         cudaFuncAttributeMaxDynamicSharedMemorySize, SMEM_BYTES);

    detect_dtype_kernel<<<1, 32>>>((const int*)ei, force64);

    const int n4 = (N * DD) / 4;
    zero_agg_kernel<<<(n4 + 255) / 256, 256>>>(n4);

    edge_kernel<<<(E + TILE - 1) / TILE, NTHREADS, SMEM_BYTES>>>(
        h, ei, We1, be1, We2, be2, out_m, N, E);

    node_kernel<<<(N + TILE - 1) / TILE, NTHREADS, SMEM_BYTES>>>(
        h, Wn1, bn1, Wn2, bn2, out_h, N);
}

// round 13
// speedup vs baseline: 1.4623x; 1.4623x over previous
#include <cuda_runtime.h>
#include <cuda_bf16.h>
#include <cstdint>

// ---------------------------------------------------------------------------
// GCL layer. Edge MLP on HMMA (mma.sync bf16, 2-way split => 3 passes, fp32
// accum in registers). Node MLP on the validated scalar FFMA path.
// Outputs (d_out): h_out [N,128] then mij [E,128], fp32.
// ---------------------------------------------------------------------------

#define DD 128
#define TILE 128
#define MAXN 50000
#define NORM_INV 0.01f

__device__ float g_agg[(size_t)MAXN * DD];   // scatter-sum scratch
__device__ int g_is64;                       // edge_index dtype flag

// Pre-swizzled bf16-split weight images, 32KB each: [128 n-rows x 128 k] bf16,
// row stride 256B, 16B-chunk XOR swizzle: off = n*256 + ((k>>3 ^ (n&7))<<4) + (k&7)*2
__device__ float4 g_B1img[2][2][2048];       // [k-chunk][hi/lo]
__device__ float4 g_B2img[2][2048];          // [hi/lo]

__device__ __forceinline__ float silu_f(float x) { return x / (1.0f + __expf(-x)); }

__device__ __forceinline__ uint32_t smem_u32(const void* p) {
    uint32_t a;
    asm("{ .reg .u64 t; cvta.to.shared.u64 t, %1; cvt.u32.u64 %0, t; }" : "=r"(a) : "l"(p));
    return a;
}

__device__ __forceinline__ void ldmx4(uint32_t* r, uint32_t addr) {
    asm volatile("ldmatrix.sync.aligned.m8n8.x4.shared.b16 {%0,%1,%2,%3}, [%4];"
                 : "=r"(r[0]), "=r"(r[1]), "=r"(r[2]), "=r"(r[3]) : "r"(addr));
}

__device__ __forceinline__ void mma_bf16(float* d, const uint32_t* a,
                                         uint32_t b0, uint32_t b1) {
    asm volatile(
        "mma.sync.aligned.m16n8k16.row.col.f32.bf16.bf16.f32 "
        "{%0,%1,%2,%3}, {%4,%5,%6,%7}, {%8,%9}, {%0,%1,%2,%3};"
        : "+f"(d[0]), "+f"(d[1]), "+f"(d[2]), "+f"(d[3])
        : "r"(a[0]), "r"(a[1]), "r"(a[2]), "r"(a[3]), "r"(b0), "r"(b1));
}

__device__ __forceinline__ uint32_t pack_bf16x2(float a, float b) {
    __nv_bfloat162 t = __floats2bfloat162_rn(a, b);
    return *(uint32_t*)&t;
}

// ---------------------------------------------------------------------------
// setup kernels
// ---------------------------------------------------------------------------
__global__ void detect_dtype_kernel(const int* __restrict__ ei, int force64) {
    if (threadIdx.x == 0 && blockIdx.x == 0) {
        if (force64) { g_is64 = 1; return; }
        int is64 = 1;
        for (int i = 0; i < 64; i++)
            if (ei[2 * i + 1] != 0) { is64 = 0; break; }
        g_is64 = is64;
    }
}

__global__ void zero_agg_kernel(int n4) {
    int i = blockIdx.x * blockDim.x + threadIdx.x;
    if (i < n4) ((float4*)g_agg)[i] = make_float4(0.f, 0.f, 0.f, 0.f);
}

__global__ void prep_weights(const float* __restrict__ We1,
                             const float* __restrict__ We2) {
    int t = blockIdx.x * blockDim.x + threadIdx.x;   // 49152 threads
    if (t < 32768) {
        int c = t >> 14, rem = t & 16383;
        int kk = rem >> 7, n = rem & 127;
        float v = We1[(size_t)(c * 128 + kk) * 128 + n];
        __nv_bfloat16 hi = __float2bfloat16_rn(v);
        __nv_bfloat16 lo = __float2bfloat16_rn(v - __bfloat162float(hi));
        uint32_t b = (uint32_t)(n * 256 + (((kk >> 3) ^ (n & 7)) << 4) + (kk & 7) * 2);
        *(unsigned short*)((char*)g_B1img[c][0] + b) = __bfloat16_as_ushort(hi);
        *(unsigned short*)((char*)g_B1img[c][1] + b) = __bfloat16_as_ushort(lo);
    } else if (t < 49152) {
        int rem = t - 32768;
        int kk = rem >> 7, n = rem & 127;
        float v = We2[(size_t)kk * 128 + n];
        __nv_bfloat16 hi = __float2bfloat16_rn(v);
        __nv_bfloat16 lo = __float2bfloat16_rn(v - __bfloat162float(hi));
        uint32_t b = (uint32_t)(n * 256 + (((kk >> 3) ^ (n & 7)) << 4) + (kk & 7) * 2);
        *(unsigned short*)((char*)g_B2img[0] + b) = __bfloat16_as_ushort(hi);
        *(unsigned short*)((char*)g_B2img[1] + b) = __bfloat16_as_ushort(lo);
    }
}

// ---------------------------------------------------------------------------
// edge kernel (HMMA). 512 threads = 16 warps, warp grid 4(M) x 4(N).
// SMEM: Ri[128] | Ci[128] | be1 | be2 | A_hi 32K | A_lo 32K | B_hi 32K | B_lo 32K
// ---------------------------------------------------------------------------
#define ESM_RI 0
#define ESM_CI 512
#define ESM_BE1 1024
#define ESM_BE2 1536
#define ESM_A_HI 2048
#define ESM_A_LO 34816
#define ESM_B_HI 67584
#define ESM_B_LO 100352
#define ESM_TOTAL 133120

// gather + bf16-split 128x128 fp32 rows into swizzled A_hi/A_lo images
__device__ __forceinline__ void fill_A(char* smem, const float* __restrict__ h,
                                       const int* __restrict__ idx, int tid) {
    const int row = tid >> 2, q = tid & 3;              // 128 rows x 4 quarters
    const float* src = h + (size_t)idx[row] * DD + q * 32;
    char* aHi = smem + ESM_A_HI;
    char* aLo = smem + ESM_A_LO;
#pragma unroll
    for (int j = 0; j < 8; j++) {
        float4 v = *(const float4*)(src + j * 4);
        __nv_bfloat16 h0 = __float2bfloat16_rn(v.x), h1 = __float2bfloat16_rn(v.y);
        __nv_bfloat16 h2 = __float2bfloat16_rn(v.z), h3 = __float2bfloat16_rn(v.w);
        float l0f = v.x - __bfloat162float(h0), l1f = v.y - __bfloat162float(h1);
        float l2f = v.z - __bfloat162float(h2), l3f = v.w - __bfloat162float(h3);
        uint32_t hw0 = (uint32_t)__bfloat16_as_ushort(h0) | ((uint32_t)__bfloat16_as_ushort(h1) << 16);
        uint32_t hw1 = (uint32_t)__bfloat16_as_ushort(h2) | ((uint32_t)__bfloat16_as_ushort(h3) << 16);
        uint32_t lw0 = pack_bf16x2(l0f, l1f);
        uint32_t lw1 = pack_bf16x2(l2f, l3f);
        int chunk = q * 4 + (j >> 1);
        uint32_t off = (uint32_t)(row * 256 + ((chunk ^ (row & 7)) << 4) + (j & 1) * 8);
        *(uint2*)(aHi + off) = make_uint2(hw0, hw1);
        *(uint2*)(aLo + off) = make_uint2(lw0, lw1);
    }
}

__device__ __forceinline__ void copy_B(char* smem, const float4* __restrict__ srcHi,
                                       const float4* __restrict__ srcLo, int tid) {
    float4* dHi = (float4*)(smem + ESM_B_HI);
    float4* dLo = (float4*)(smem + ESM_B_LO);
#pragma unroll
    for (int i = 0; i < 4; i++) {
        int j = tid + i * 512;
        dHi[j] = srcHi[j];
        dLo[j] = srcLo[j];
    }
}

// One K=128 layer chunk, 3 bf16-split passes, fp32 register accumulate.
__device__ __forceinline__ void mma_layer(float acc[2][4][4], uint32_t sb,
                                          int row_a, int row_b, int ka, int kb) {
#pragma unroll
    for (int pass = 0; pass < 3; pass++) {
        const uint32_t sbA = sb + ((pass < 2) ? ESM_A_HI : ESM_A_LO);
        const uint32_t sbB = sb + ((pass == 1) ? ESM_B_LO : ESM_B_HI);
#pragma unroll
        for (int ks = 0; ks < 8; ks++) {
            uint32_t a[2][4], b[2][4];
#pragma unroll
            for (int mt = 0; mt < 2; mt++)
                ldmx4(a[mt], sbA + (uint32_t)((row_a + mt * 16) * 256 +
                      (((ks * 2 + ka) ^ (row_a & 7)) << 4)));
#pragma unroll
            for (int nt = 0; nt < 2; nt++)
                ldmx4(b[nt], sbB + (uint32_t)((row_b + nt * 16) * 256 +
                      (((ks * 2 + kb) ^ (row_b & 7)) << 4)));
#pragma unroll
            for (int mt = 0; mt < 2; mt++)
#pragma unroll
                for (int nt = 0; nt < 2; nt++) {
                    mma_bf16(acc[mt][nt * 2 + 0], a[mt], b[nt][0], b[nt][1]);
                    mma_bf16(acc[mt][nt * 2 + 1], a[mt], b[nt][2], b[nt][3]);
                }
        }
    }
}

__global__ void __launch_bounds__(512, 1)
edge_kernel(const float* __restrict__ h, const void* __restrict__ ei,
            const float* __restrict__ be1, const float* __restrict__ be2,
            float* __restrict__ out_m, int N, int E) {
    extern __shared__ char smem[];
    const uint32_t sb = smem_u32(smem);
    const int tid = threadIdx.x;
    const int wid = tid >> 5, lane = tid & 31;
    const int warp_m = wid & 3, warp_n = wid >> 2;
    const long long eb = (long long)blockIdx.x * TILE;

    int* Ri = (int*)(smem + ESM_RI);
    int* Ci = (int*)(smem + ESM_CI);
    if (tid < TILE) {
        long long e = eb + tid;
        if (e >= E) e = E - 1;
        int r, c;
        if (g_is64) {
            const long long* p = (const long long*)ei;
            r = (int)p[e];
            c = (int)p[(long long)E + e];
        } else {
            const int* p = (const int*)ei;
            r = p[e];
            c = p[E + e];
        }
        Ri[tid] = min(max(r, 0), N - 1);
        Ci[tid] = min(max(c, 0), N - 1);
        ((float*)(smem + ESM_BE1))[tid] = be1[tid];
        ((float*)(smem + ESM_BE2))[tid] = be2[tid];
    }
    __syncthreads();

    // per-thread ldmatrix lane geometry
    const int lg = lane >> 3, lr = lane & 7;
    const int row_a = warp_m * 32 + (lg & 1) * 8 + lr;   // + mt*16
    const int ka = lg >> 1;
    const int row_b = warp_n * 32 + (lg >> 1) * 8 + lr;  // + nt*16
    const int kb = lg & 1;
    // epilogue fragment geometry
    const int lrow = lane >> 2, lcol2 = (lane & 3) * 2;

    float acc[2][4][4];
#pragma unroll
    for (int i = 0; i < 2; i++)
#pragma unroll
        for (int j = 0; j < 4; j++)
#pragma unroll
            for (int k = 0; k < 4; k++) acc[i][j][k] = 0.f;

    // ---- layer 1 chunk 0 (src endpoints) ----
    fill_A(smem, h, Ri, tid);
    copy_B(smem, g_B1img[0][0], g_B1img[0][1], tid);
    __syncthreads();
    mma_layer(acc, sb, row_a, row_b, ka, kb);
    __syncthreads();

    // ---- layer 1 chunk 1 (tgt endpoints), accumulate ----
    fill_A(smem, h, Ci, tid);
    copy_B(smem, g_B1img[1][0], g_B1img[1][1], tid);
    __syncthreads();
    mma_layer(acc, sb, row_a, row_b, ka, kb);
    __syncthreads();

    // ---- D1 epilogue: bias + SiLU -> split H back into A images ----
    {
        const float* b1s = (const float*)(smem + ESM_BE1);
        char* aHi = smem + ESM_A_HI;
        char* aLo = smem + ESM_A_LO;
#pragma unroll
        for (int mt = 0; mt < 2; mt++)
#pragma unroll
            for (int j = 0; j < 4; j++) {
                const int col = warp_n * 32 + j * 8 + lcol2;
                const int chunk = col >> 3;
#pragma unroll
                for (int half = 0; half < 2; half++) {
                    const int row = warp_m * 32 + mt * 16 + lrow + half * 8;
                    float f0 = silu_f(acc[mt][j][half * 2 + 0] + b1s[col]);
                    float f1 = silu_f(acc[mt][j][half * 2 + 1] + b1s[col + 1]);
                    __nv_bfloat16 h0 = __float2bfloat16_rn(f0);
                    __nv_bfloat16 h1 = __float2bfloat16_rn(f1);
                    uint32_t hw = (uint32_t)__bfloat16_as_ushort(h0) |
                                  ((uint32_t)__bfloat16_as_ushort(h1) << 16);
                    uint32_t lw = pack_bf16x2(f0 - __bfloat162float(h0),
                                              f1 - __bfloat162float(h1));
                    uint32_t off = (uint32_t)(row * 256 + ((chunk ^ (row & 7)) << 4) +
                                              (col & 7) * 2);
                    *(uint32_t*)(aHi + off) = hw;
                    *(uint32_t*)(aLo + off) = lw;
                }
            }
    }
    copy_B(smem, g_B2img[0], g_B2img[1], tid);
#pragma unroll
    for (int i = 0; i < 2; i++)
#pragma unroll
        for (int j = 0; j < 4; j++)
#pragma unroll
            for (int k = 0; k < 4; k++) acc[i][j][k] = 0.f;
    __syncthreads();

    // ---- layer 2 ----
    mma_layer(acc, sb, row_a, row_b, ka, kb);

    // ---- D2 epilogue: bias + SiLU -> mij + scatter-add ----
    {
        const float* b2s = (const float*)(smem + ESM_BE2);
#pragma unroll
        for (int mt = 0; mt < 2; mt++)
#pragma unroll
            for (int half = 0; half < 2; half++) {
                const int row = warp_m * 32 + mt * 16 + lrow + half * 8;
                const long long eg = eb + row;
                if (eg < E) {
                    const int ridx = Ri[row];
#pragma unroll
                    for (int j = 0; j < 4; j++) {
                        const int col = warp_n * 32 + j * 8 + lcol2;
                        float f0 = silu_f(acc[mt][j][half * 2 + 0] + b2s[col]);
                        float f1 = silu_f(acc[mt][j][half * 2 + 1] + b2s[col + 1]);
                        *(float2*)(out_m + (size_t)eg * DD + col) = make_float2(f0, f1);
                        float* ap = g_agg + (size_t)ridx * DD + col;
                        asm volatile("red.global.add.v2.f32 [%0], {%1,%2};"
                                     :: "l"(ap), "f"(f0), "f"(f1) : "memory");
                    }
                }
            }
    }
}

// ---------------------------------------------------------------------------
// node kernel (scalar FFMA path, unchanged from passing round-3 kernel)
// ---------------------------------------------------------------------------
#define NTHREADS 256
#define XS_STRIDE 33
#define HS_STRIDE 130
#define SMEM_FLOATS (TILE * XS_STRIDE + 32 * DD + TILE * HS_STRIDE)
#define NSMEM_BYTES (SMEM_FLOATS * 4 + 2 * TILE * 4)

__device__ __forceinline__ void fma2(unsigned long long& d, unsigned long long a,
                                     unsigned long long b) {
    asm("fma.rn.f32x2 %0, %1, %2, %0;" : "+l"(d) : "l"(a), "l"(b));
}
__device__ __forceinline__ unsigned long long bcast2(unsigned int a) {
    unsigned long long r;
    asm("mov.b64 %0, {%1, %2};" : "=l"(r) : "r"(a), "r"(a));
    return r;
}
__device__ __forceinline__ void unpack2(unsigned long long v, float& lo, float& hi) {
    unsigned int a, b;
    asm("mov.b64 {%0, %1}, %2;" : "=r"(a), "=r"(b) : "l"(v));
    lo = __uint_as_float(a);
    hi = __uint_as_float(b);
}

__device__ __forceinline__ void mma_chunk(unsigned long long acc[8][4],
                                          const float* __restrict__ A, int astride,
                                          const float* __restrict__ Ws,
                                          int te, int tn) {
#pragma unroll 4
    for (int kk = 0; kk < 32; kk++) {
        const float* wrow = Ws + kk * DD + tn * 8;
        ulonglong2 q0 = *(const ulonglong2*)(wrow);
        ulonglong2 q1 = *(const ulonglong2*)(wrow + 4);
#pragma unroll
        for (int i = 0; i < 8; i++) {
            unsigned long long ap = bcast2(__float_as_uint(A[(te * 8 + i) * astride + kk]));
            fma2(acc[i][0], ap, q0.x);
            fma2(acc[i][1], ap, q0.y);
            fma2(acc[i][2], ap, q1.x);
            fma2(acc[i][3], ap, q1.y);
        }
    }
}

__global__ void __launch_bounds__(NTHREADS, 2)
node_kernel(const float* __restrict__ h,
            const float* __restrict__ Wn1, const float* __restrict__ bn1,
            const float* __restrict__ Wn2, const float* __restrict__ bn2,
            float* __restrict__ out_h, int N) {
    extern __shared__ float smf[];
    float* Xs = smf;
    float* Ws = Xs + TILE * XS_STRIDE;
    float* Hs = Ws + 32 * DD;

    const int tid = threadIdx.x;
    const int tn = tid & 15;
    const int te = tid >> 4;
    const int nb = blockIdx.x * TILE;

    float b1v[8], b2v[8];
    {
        float4 t0 = *(const float4*)(bn1 + tn * 8);
        float4 t1 = *(const float4*)(bn1 + tn * 8 + 4);
        b1v[0]=t0.x; b1v[1]=t0.y; b1v[2]=t0.z; b1v[3]=t0.w;
        b1v[4]=t1.x; b1v[5]=t1.y; b1v[6]=t1.z; b1v[7]=t1.w;
        float4 u0 = *(const float4*)(bn2 + tn * 8);
        float4 u1 = *(const float4*)(bn2 + tn * 8 + 4);
        b2v[0]=u0.x; b2v[1]=u0.y; b2v[2]=u0.z; b2v[3]=u0.w;
        b2v[4]=u1.x; b2v[5]=u1.y; b2v[6]=u1.z; b2v[7]=u1.w;
    }

    unsigned long long acc[8][4];
#pragma unroll
    for (int i = 0; i < 8; i++)
#pragma unroll
        for (int j = 0; j < 4; j++) acc[i][j] = 0ULL;

#pragma unroll 1
    for (int kc = 0; kc < 8; kc++) {
        __syncthreads();
        const int koff = (kc & 3) * 32;
        const bool from_h = (kc < 4);
        const float* src = from_h ? h : (const float*)g_agg;
        const float scale = from_h ? 1.0f : NORM_INV;
#pragma unroll
        for (int l = 0; l < 4; l++) {
            int lin = tid + l * NTHREADS;
            int e = lin >> 3, seg = lin & 7;
            int node = nb + e;
            if (node >= N) node = N - 1;
            float4 v = *(const float4*)(src + (size_t)node * DD + koff + seg * 4);
            float* dst = Xs + e * XS_STRIDE + seg * 4;
            dst[0] = v.x * scale; dst[1] = v.y * scale;
            dst[2] = v.z * scale; dst[3] = v.w * scale;
        }
#pragma unroll
        for (int l = 0; l < 4; l++) {
            int lin = tid + l * NTHREADS;
            int kk = lin >> 5, n4 = lin & 31;
            *(float4*)(Ws + kk * DD + n4 * 4) =
                *(const float4*)(Wn1 + (size_t)(kc * 32 + kk) * DD + n4 * 4);
        }
        __syncthreads();
        mma_chunk(acc, Xs, XS_STRIDE, Ws, te, tn);
    }

#pragma unroll
    for (int i = 0; i < 8; i++) {
        float v[8];
        unpack2(acc[i][0], v[0], v[1]);
        unpack2(acc[i][1], v[2], v[3]);
        unpack2(acc[i][2], v[4], v[5]);
        unpack2(acc[i][3], v[6], v[7]);
#pragma unroll
        for (int j = 0; j < 8; j++)
            Hs[(te * 8 + i) * HS_STRIDE + tn * 8 + j] = silu_f(v[j] + b1v[j]);
#pragma unroll
        for (int j = 0; j < 4; j++) acc[i][j] = 0ULL;
    }

#pragma unroll 1
    for (int kc = 0; kc < 4; kc++) {
        __syncthreads();
#pragma unroll
        for (int l = 0; l < 4; l++) {
            int lin = tid + l * NTHREADS;
            int kk = lin >> 5, n4 = lin & 31;
            *(float4*)(Ws + kk * DD + n4 * 4) =
                *(const float4*)(Wn2 + (size_t)(kc * 32 + kk) * DD + n4 * 4);
        }
        __syncthreads();
        mma_chunk(acc, Hs + kc * 32, HS_STRIDE, Ws, te, tn);
    }

#pragma unroll
    for (int i = 0; i < 8; i++) {
        int node = nb + te * 8 + i;
        if (node < N) {
            float v[8];
            unpack2(acc[i][0], v[0], v[1]);
            unpack2(acc[i][1], v[2], v[3]);
            unpack2(acc[i][2], v[4], v[5]);
            unpack2(acc[i][3], v[6], v[7]);
            const float4 r0 = *(const float4*)(h + (size_t)node * DD + tn * 8);
            const float4 r1 = *(const float4*)(h + (size_t)node * DD + tn * 8 + 4);
            v[0] += b2v[0] + r0.x; v[1] += b2v[1] + r0.y;
            v[2] += b2v[2] + r0.z; v[3] += b2v[3] + r0.w;
            v[4] += b2v[4] + r1.x; v[5] += b2v[5] + r1.y;
            v[6] += b2v[6] + r1.z; v[7] += b2v[7] + r1.w;
            float4* dst = (float4*)(out_h + (size_t)node * DD + tn * 8);
            dst[0] = make_float4(v[0], v[1], v[2], v[3]);
            dst[1] = make_float4(v[4], v[5], v[6], v[7]);
        }
    }
}

// ---------------------------------------------------------------------------
extern "C" void kernel_launch(void* const* d_in, const int* in_sizes, int n_in,
                              void* d_out, int out_size) {
    const float* h   = (const float*)d_in[0];
    const void*  ei  = d_in[1];
    const float* We1 = (const float*)d_in[2];
    const float* be1 = (const float*)d_in[3];
    const float* We2 = (const float*)d_in[4];
    const float* be2 = (const float*)d_in[5];
    const float* Wn1 = (const float*)d_in[6];
    const float* bn1 = (const float*)d_in[7];
    const float* Wn2 = (const float*)d_in[8];
    const float* bn2 = (const float*)d_in[9];

    const int N = in_sizes[0] / DD;
    const int E = out_size / DD - N;
    const int force64 = (in_sizes[1] == 4 * E) ? 1 : 0;

    float* out_h = (float*)d_out;
    float* out_m = out_h + (size_t)N * DD;

    cudaFuncSetAttribute(edge_kernel,
                         cudaFuncAttributeMaxDynamicSharedMemorySize, ESM_TOTAL);
    cudaFuncSetAttribute(node_kernel,
                         cudaFuncAttributeMaxDynamicSharedMemorySize, NSMEM_BYTES);

    detect_dtype_kernel<<<1, 32>>>((const int*)ei, force64);
    prep_weights<<<192, 256>>>(We1, We2);

    const int n4 = (N * DD) / 4;
    zero_agg_kernel<<<(n4 + 255) / 256, 256>>>(n4);

    edge_kernel<<<(E + TILE - 1) / TILE, 512, ESM_TOTAL>>>(
        h, ei, be1, be2, out_m, N, E);

    node_kernel<<<(N + TILE - 1) / TILE, NTHREADS, NSMEM_BYTES>>>(
        h, Wn1, bn1, Wn2, bn2, out_h, N);
}